// round 14
// baseline (speedup 1.0000x reference)
#include <cuda_runtime.h>
#include <cuda_fp16.h>
#include <math.h>

#define LCc 1024
#define LQq 512
#define NB  64
#define ND  256

typedef unsigned int u32;

__device__ __half g_Ch [(size_t)LCc * NB * ND];   // [c][b][d]            (k1 A)
__device__ __half g_C2 [(size_t)LCc * NB * ND];   // [c/2][b][d][c&1]     (k4 B)
__device__ __half g_Qwh[(size_t)LQq * NB * ND];   // [q][b][d]  Q*wml     (k1 B)
__device__ __half g_Q2 [(size_t)LQq * NB * ND];   // [q/2][b][d][q&1]     (k5 Bq)
__device__ __half g_Eh [(size_t)NB * LCc * LQq];  // [b][c][q]            (k5 A)
__device__ __half g_E2 [(size_t)NB * LCc * LQq];  // [b][c/2][q][c&1]     (k4 A)
__device__ __half g_M2 [(size_t)NB * LQq * ND];   // [b][q/2][d][q&1]     (k5 Bm)
__device__ float g_sub0[NB * LCc];
__device__ float g_sub1[NB * LQq];
__device__ float g_rsum[NB * LCc];
__device__ float g_csum2[NB * LQq];

// ---------------- helpers -----------------------------------------------------
__device__ __forceinline__ void mma16(float4& d,
        u32 a0, u32 a1, u32 a2, u32 a3, u32 b0, u32 b1) {
    asm volatile("mma.sync.aligned.m16n8k16.row.col.f32.f16.f16.f32 "
        "{%0,%1,%2,%3}, {%4,%5,%6,%7}, {%8,%9}, {%0,%1,%2,%3};"
        : "+f"(d.x), "+f"(d.y), "+f"(d.z), "+f"(d.w)
        : "r"(a0), "r"(a1), "r"(a2), "r"(a3), "r"(b0), "r"(b1));
}
__device__ __forceinline__ u32 smem_u32(const void* p) {
    u32 a; asm("{ .reg .u64 t; cvta.to.shared.u64 t, %1; cvt.u32.u64 %0, t; }"
               : "=r"(a) : "l"(p));
    return a;
}
__device__ __forceinline__ void cpa16(u32 dst, const void* src) {
    asm volatile("cp.async.cg.shared.global [%0], [%1], 16;" :: "r"(dst), "l"(src) : "memory");
}
__device__ __forceinline__ void cpa_commit() {
    asm volatile("cp.async.commit_group;" ::: "memory");
}
template<int N>
__device__ __forceinline__ void cpa_wait() {
    asm volatile("cp.async.wait_group %0;" :: "n"(N) : "memory");
}
__device__ __forceinline__ __half h_rn(float f) { return __float2half_rn(f); }
__device__ __forceinline__ float exp2p(float e) {
    float r = rintf(e);
    float f = e - r;
    float p = 1.33335581464e-3f;
    p = fmaf(p, f, 9.61812910763e-3f);
    p = fmaf(p, f, 5.55041086648e-2f);
    p = fmaf(p, f, 2.40226506959e-1f);
    p = fmaf(p, f, 6.93147180560e-1f);
    p = fmaf(p, f, 1.0f);
    int ei = (int)r;
    return p * __int_as_float((ei + 127) << 23);
}
#define L2E 1.44269504088896340736f

// ---------------- small kernels ------------------------------------------------
__global__ void k_init() {
    int i = blockIdx.x * blockDim.x + threadIdx.x;
    if (i < NB * LQq) { g_csum2[i] = 0.f; g_sub1[i] = 0.f; }
    if (i < NB * LCc) { g_rsum[i] = 0.f;  g_sub0[i] = 0.f; }
}

// ---- fused prepass: fp16 conversions + interleaved copies + sub0/sub1 dots ----
__global__ __launch_bounds__(256) void k0_all(const float* __restrict__ C,
                                              const float* __restrict__ Q,
                                              const float* __restrict__ w4C,
                                              const float* __restrict__ w4Q,
                                              const float* __restrict__ wml) {
    const int bid = blockIdx.x, tid = threadIdx.x;
    if (bid < 8192) {   // ---- C part ----
        int i = bid * 256 + tid;
        int d  = (i & 63) * 4;
        int b  = (i >> 6) & 63;
        int cp = i >> 12;
        float4 v0 = *(const float4*)(C + ((size_t)(2 * cp)     * NB + b) * ND + d);
        float4 v1 = *(const float4*)(C + ((size_t)(2 * cp + 1) * NB + b) * ND + d);
        __half2* c0 = (__half2*)(g_Ch + ((size_t)(2 * cp)     * NB + b) * ND + d);
        __half2* c1 = (__half2*)(g_Ch + ((size_t)(2 * cp + 1) * NB + b) * ND + d);
        c0[0] = __floats2half2_rn(v0.x, v0.y);
        c0[1] = __floats2half2_rn(v0.z, v0.w);
        c1[0] = __floats2half2_rn(v1.x, v1.y);
        c1[1] = __floats2half2_rn(v1.z, v1.w);
        __half2* c2 = (__half2*)(g_C2 + (((size_t)cp * NB + b) * ND + d) * 2);
        c2[0] = __floats2half2_rn(v0.x, v1.x);
        c2[1] = __floats2half2_rn(v0.y, v1.y);
        c2[2] = __floats2half2_rn(v0.z, v1.z);
        c2[3] = __floats2half2_rn(v0.w, v1.w);
        float4 wc = *(const float4*)(w4C + d);
        float d0 = v0.x * wc.x + v0.y * wc.y + v0.z * wc.z + v0.w * wc.w;
        float d1 = v1.x * wc.x + v1.y * wc.y + v1.z * wc.z + v1.w * wc.w;
#pragma unroll
        for (int off = 16; off; off >>= 1) {
            d0 += __shfl_xor_sync(0xffffffffu, d0, off);
            d1 += __shfl_xor_sync(0xffffffffu, d1, off);
        }
        if ((tid & 31) == 0) {
            atomicAdd(&g_sub0[b * LCc + 2 * cp], d0);
            atomicAdd(&g_sub0[b * LCc + 2 * cp + 1], d1);
        }
    } else {            // ---- Q part ----
        int i = (bid - 8192) * 256 + tid;
        int d  = (i & 63) * 4;
        int b  = (i >> 6) & 63;
        int qp = i >> 12;
        float4 ww = ((const float4*)wml)[i & 63];
        float4 v0 = *(const float4*)(Q + ((size_t)(2 * qp)     * NB + b) * ND + d);
        float4 v1 = *(const float4*)(Q + ((size_t)(2 * qp + 1) * NB + b) * ND + d);
        __half2* w0 = (__half2*)(g_Qwh + ((size_t)(2 * qp)     * NB + b) * ND + d);
        __half2* w1 = (__half2*)(g_Qwh + ((size_t)(2 * qp + 1) * NB + b) * ND + d);
        w0[0] = __floats2half2_rn(v0.x * ww.x, v0.y * ww.y);
        w0[1] = __floats2half2_rn(v0.z * ww.z, v0.w * ww.w);
        w1[0] = __floats2half2_rn(v1.x * ww.x, v1.y * ww.y);
        w1[1] = __floats2half2_rn(v1.z * ww.z, v1.w * ww.w);
        __half2* q2 = (__half2*)(g_Q2 + (((size_t)qp * NB + b) * ND + d) * 2);
        q2[0] = __floats2half2_rn(v0.x, v1.x);
        q2[1] = __floats2half2_rn(v0.y, v1.y);
        q2[2] = __floats2half2_rn(v0.z, v1.z);
        q2[3] = __floats2half2_rn(v0.w, v1.w);
        float4 wq = *(const float4*)(w4Q + d);
        float d0 = v0.x * wq.x + v0.y * wq.y + v0.z * wq.z + v0.w * wq.w;
        float d1 = v1.x * wq.x + v1.y * wq.y + v1.z * wq.z + v1.w * wq.w;
#pragma unroll
        for (int off = 16; off; off >>= 1) {
            d0 += __shfl_xor_sync(0xffffffffu, d0, off);
            d1 += __shfl_xor_sync(0xffffffffu, d1, off);
        }
        if ((tid & 31) == 0) {
            atomicAdd(&g_sub1[b * LQq + 2 * qp], d0);
            atomicAdd(&g_sub1[b * LQq + 2 * qp + 1], d1);
        }
    }
}

// ---- k1: E = exp(Ch @ Qwh^T + sub0 + sub1 + bias) -> g_Eh + g_E2; fused sums --
// (unchanged from R13 - known good)
__global__ __launch_bounds__(256, 2) void k1_scores(const float* __restrict__ bias) {
    __shared__ __half As[2][128][40];
    __shared__ __half Bs[2][128][40];
    const int tid = threadIdx.x, lane = tid & 31, w = tid >> 5;
    const int g = lane >> 2, t = lane & 3;
    const int b = blockIdx.z, c0 = blockIdx.y * 128, q0 = blockIdx.x * 128;
    const int mbase = (w >> 2) * 64, nbase = (w & 3) * 32;
    const int row = tid >> 1, sg = (tid & 1) * 16;
    const __half* Ag = g_Ch + ((size_t)(c0 + row) * NB + b) * ND + sg;
    const __half* Bg = g_Qwh + ((size_t)(q0 + row) * NB + b) * ND + sg;
    const u32 Ad = smem_u32(&As[0][row][sg]);
    const u32 Bd = smem_u32(&Bs[0][row][sg]);
    cpa16(Ad, Ag); cpa16(Ad + 16, Ag + 8);
    cpa16(Bd, Bg); cpa16(Bd + 16, Bg + 8);
    cpa_commit();
    float4 acc[4][4] = {};
    for (int ch = 0; ch < 8; ++ch) {
        const int p = ch & 1;
        if (ch < 7) {
            const int ko = (ch + 1) * 32;
            const u32 off = (u32)((p ^ 1) * 10240);
            cpa16(Ad + off, Ag + ko); cpa16(Ad + off + 16, Ag + ko + 8);
            cpa16(Bd + off, Bg + ko); cpa16(Bd + off + 16, Bg + ko + 8);
            cpa_commit();
            cpa_wait<1>();
        } else cpa_wait<0>();
        __syncthreads();
#pragma unroll
        for (int kk = 0; kk < 32; kk += 16) {
            u32 af[4][4], bf[4][2];
#pragma unroll
            for (int mi = 0; mi < 4; ++mi) {
                int m = mbase + mi * 16 + g;
                af[mi][0] = *(const u32*)&As[p][m][kk + 2 * t];
                af[mi][1] = *(const u32*)&As[p][m + 8][kk + 2 * t];
                af[mi][2] = *(const u32*)&As[p][m][kk + 2 * t + 8];
                af[mi][3] = *(const u32*)&As[p][m + 8][kk + 2 * t + 8];
            }
#pragma unroll
            for (int ni = 0; ni < 4; ++ni) {
                int n = nbase + ni * 8 + g;
                bf[ni][0] = *(const u32*)&Bs[p][n][kk + 2 * t];
                bf[ni][1] = *(const u32*)&Bs[p][n][kk + 2 * t + 8];
            }
#pragma unroll
            for (int mi = 0; mi < 4; ++mi)
#pragma unroll
                for (int ni = 0; ni < 4; ++ni)
                    mma16(acc[mi][ni], af[mi][0], af[mi][1], af[mi][2], af[mi][3],
                          bf[ni][0], bf[ni][1]);
        }
        __syncthreads();
    }
    const float bv = bias[0];
    float s1x[4], s1y[4];
#pragma unroll
    for (int ni = 0; ni < 4; ++ni) {
        int q = q0 + nbase + ni * 8 + 2 * t;
        s1x[ni] = g_sub1[b * LQq + q] * L2E;
        s1y[ni] = g_sub1[b * LQq + q + 1] * L2E;
    }
    float rs0[4] = {}, rs1[4] = {}, ccx[4] = {}, ccy[4] = {};
#pragma unroll
    for (int mi = 0; mi < 4; ++mi) {
        int cA = c0 + mbase + mi * 16 + g;
        float s0a = (g_sub0[b * LCc + cA] + bv) * L2E;
        float s0b = (g_sub0[b * LCc + cA + 8] + bv) * L2E;
        __half* r0 = g_Eh + (size_t)(b * LCc + cA) * LQq + q0;
        __half* r1 = r0 + (size_t)8 * LQq;
        size_t e20 = ((size_t)(b * (LCc / 2) + (cA >> 1)) * LQq + q0) * 2 + (cA & 1);
        size_t e21 = e20 + (size_t)8 * LQq;
#pragma unroll
        for (int ni = 0; ni < 4; ++ni) {
            int q = nbase + ni * 8 + 2 * t;
            float f00 = exp2p(fmaf(acc[mi][ni].x, L2E, s0a + s1x[ni]));
            float f01 = exp2p(fmaf(acc[mi][ni].y, L2E, s0a + s1y[ni]));
            float f10 = exp2p(fmaf(acc[mi][ni].z, L2E, s0b + s1x[ni]));
            float f11 = exp2p(fmaf(acc[mi][ni].w, L2E, s0b + s1y[ni]));
            __half h00 = h_rn(f00), h01 = h_rn(f01);
            __half h10 = h_rn(f10), h11 = h_rn(f11);
            *(__half2*)(r0 + q) = __halves2half2(h00, h01);
            *(__half2*)(r1 + q) = __halves2half2(h10, h11);
            g_E2[e20 + 2 * q] = h00; g_E2[e20 + 2 * q + 2] = h01;
            g_E2[e21 + 2 * q] = h10; g_E2[e21 + 2 * q + 2] = h11;
            float v00 = __half2float(h00), v01 = __half2float(h01);
            float v10 = __half2float(h10), v11 = __half2float(h11);
            rs0[mi] += v00 + v01; rs1[mi] += v10 + v11;
            ccx[ni] += v00 + v10; ccy[ni] += v01 + v11;
        }
    }
#pragma unroll
    for (int mi = 0; mi < 4; ++mi) {
        float a = rs0[mi], c2 = rs1[mi];
        a  += __shfl_xor_sync(0xffffffffu, a, 1);  a  += __shfl_xor_sync(0xffffffffu, a, 2);
        c2 += __shfl_xor_sync(0xffffffffu, c2, 1); c2 += __shfl_xor_sync(0xffffffffu, c2, 2);
        if (t == 0) {
            int cA = c0 + mbase + mi * 16 + g;
            atomicAdd(&g_rsum[b * LCc + cA], a);
            atomicAdd(&g_rsum[b * LCc + cA + 8], c2);
        }
    }
#pragma unroll
    for (int ni = 0; ni < 4; ++ni) {
        float x = ccx[ni], y = ccy[ni];
        x += __shfl_xor_sync(0xffffffffu, x, 4);  y += __shfl_xor_sync(0xffffffffu, y, 4);
        x += __shfl_xor_sync(0xffffffffu, x, 8);  y += __shfl_xor_sync(0xffffffffu, y, 8);
        x += __shfl_xor_sync(0xffffffffu, x, 16); y += __shfl_xor_sync(0xffffffffu, y, 16);
        if (g == 0) {
            int q = q0 + nbase + ni * 8 + 2 * t;
            atomicAdd(&g_csum2[b * LQq + q], x);
            atomicAdd(&g_csum2[b * LQq + q + 1], y);
        }
    }
}

// ---- k4: M2 = (E^T @ C / colsum); 4-stage ring, 8 c-pairs per chunk ------------
__global__ __launch_bounds__(256, 2) void k4_M() {
    __shared__ __half As[4][8][264];
    __shared__ __half Bs[4][8][264];
    const int b = blockIdx.z, q0 = blockIdx.y * 128, d0 = blockIdx.x * 128;
    const int tid = threadIdx.x, lane = tid & 31, w = tid >> 5;
    const int g = lane >> 2, t = lane & 3;
    const int mbase = (w >> 2) * 64, nbase = (w & 3) * 32;
    const int r8 = tid >> 5, sg = (tid & 31) * 8;
    const __half* Ag = g_E2 + ((size_t)(b * (LCc / 2) + r8) * LQq + q0) * 2 + sg;
    const __half* Bg = g_C2 + ((size_t)(r8 * NB + b) * ND + d0) * 2 + sg;
    const size_t Astep = (size_t)8 * LQq * 2;
    const size_t Bstep = (size_t)8 * NB * ND * 2;
    const u32 Ad = smem_u32(&As[0][r8][sg]);
    const u32 Bd = smem_u32(&Bs[0][r8][sg]);
#pragma unroll
    for (int pc = 0; pc < 3; ++pc) {
        cpa16(Ad + pc * 4224, Ag + pc * Astep);
        cpa16(Bd + pc * 4224, Bg + pc * Bstep);
        cpa_commit();
    }
    float4 acc[4][4] = {};
    for (int ch = 0; ch < 64; ++ch) {
        const int p = ch & 3;
        if (ch + 2 < 64) cpa_wait<2>();
        else if (ch + 1 < 64) cpa_wait<1>();
        else cpa_wait<0>();
        __syncthreads();
        if (ch + 3 < 64) {
            const u32 off = (u32)(((ch + 3) & 3) * 4224);
            cpa16(Ad + off, Ag + (size_t)(ch + 3) * Astep);
            cpa16(Bd + off, Bg + (size_t)(ch + 3) * Bstep);
            cpa_commit();
        }
        u32 af[4][4], bf[4][2];
#pragma unroll
        for (int mi = 0; mi < 4; ++mi) {
            int m = mbase + mi * 16 + g;
            af[mi][0] = *(const u32*)&As[p][t][2 * m];
            af[mi][1] = *(const u32*)&As[p][t][2 * (m + 8)];
            af[mi][2] = *(const u32*)&As[p][t + 4][2 * m];
            af[mi][3] = *(const u32*)&As[p][t + 4][2 * (m + 8)];
        }
#pragma unroll
        for (int ni = 0; ni < 4; ++ni) {
            int n = nbase + ni * 8 + g;
            bf[ni][0] = *(const u32*)&Bs[p][t][2 * n];
            bf[ni][1] = *(const u32*)&Bs[p][t + 4][2 * n];
        }
#pragma unroll
        for (int mi = 0; mi < 4; ++mi)
#pragma unroll
            for (int ni = 0; ni < 4; ++ni)
                mma16(acc[mi][ni], af[mi][0], af[mi][1], af[mi][2], af[mi][3],
                      bf[ni][0], bf[ni][1]);
    }
#pragma unroll
    for (int mi = 0; mi < 4; ++mi) {
        int qA = q0 + mbase + mi * 16 + g;
        float i0 = 1.0f / g_csum2[b * LQq + qA];
        float i1 = 1.0f / g_csum2[b * LQq + qA + 8];
        size_t m0b = ((size_t)(b * (LQq / 2) + (qA >> 1)) * ND + d0) * 2 + (qA & 1);
        size_t m1b = m0b + (size_t)8 * ND;
#pragma unroll
        for (int ni = 0; ni < 4; ++ni) {
            int d = nbase + ni * 8 + 2 * t;
            g_M2[m0b + 2 * d]     = h_rn(acc[mi][ni].x * i0);
            g_M2[m0b + 2 * d + 2] = h_rn(acc[mi][ni].y * i0);
            g_M2[m1b + 2 * d]     = h_rn(acc[mi][ni].z * i1);
            g_M2[m1b + 2 * d + 2] = h_rn(acc[mi][ni].w * i1);
        }
    }
}

// ---- k5: A = S1@Q, B_ = S1@M; 4-stage ring, 16 q per chunk ---------------------
__global__ __launch_bounds__(256, 2) void k5_out(const float* __restrict__ C,
                                                 float* __restrict__ out) {
    __shared__ __align__(16) char sm5[43008];
    __half (*As)[128][24] = (__half(*)[128][24])sm5;              // 4 x 6144
    __half (*Bq)[8][144]  = (__half(*)[8][144])(sm5 + 24576);     // 4 x 2304
    __half (*Bm)[8][144]  = (__half(*)[8][144])(sm5 + 33792);     // 4 x 2304
    float (*Cs)[65]       = (float(*)[65])sm5;                    // epilogue
    float (*Tr)[69]       = (float(*)[69])(sm5 + 16640);          // epilogue
    const int b = blockIdx.z, c0 = blockIdx.y * 128, d0 = blockIdx.x * 64;
    const int tid = threadIdx.x, lane = tid & 31, w = tid >> 5;
    const int g = lane >> 2, t = lane & 3;
    const int wr = w >> 1, wc = w & 1;
    const int mbase = wr * 32, nbase = wc * 32;
    const int rowc = tid >> 1, sgA = (tid & 1) * 8;
    const int isM = tid >> 7, rB = (tid >> 4) & 7, sB = (tid & 15) * 8;
    const __half* Ag = g_Eh + (size_t)(b * LCc + c0 + rowc) * LQq + sgA;
    const __half* Qg = g_Q2 + ((size_t)(rB * NB + b) * ND + d0) * 2 + sB;
    const __half* Mg = g_M2 + ((size_t)(b * (LQq / 2) + rB) * ND + d0) * 2 + sB;
    const __half* Bg = isM ? Mg : Qg;
    const size_t Bstep = isM ? (size_t)8 * ND * 2 : (size_t)8 * NB * ND * 2;
    const u32 Ad = smem_u32(&As[0][rowc][sgA]);
    const u32 Bd = isM ? smem_u32(&Bm[0][rB][sB]) : smem_u32(&Bq[0][rB][sB]);
#pragma unroll
    for (int pc = 0; pc < 3; ++pc) {
        cpa16(Ad + pc * 6144, Ag + pc * 16);
        cpa16(Bd + pc * 2304, Bg + pc * Bstep);
        cpa_commit();
    }
    float4 accA[2][4] = {}, accB[2][4] = {};
    for (int ch = 0; ch < 32; ++ch) {
        const int p = ch & 3;
        if (ch + 2 < 32) cpa_wait<2>();
        else if (ch + 1 < 32) cpa_wait<1>();
        else cpa_wait<0>();
        __syncthreads();
        if (ch + 3 < 32) {
            cpa16(Ad + (u32)(((ch + 3) & 3) * 6144), Ag + (ch + 3) * 16);
            cpa16(Bd + (u32)(((ch + 3) & 3) * 2304), Bg + (size_t)(ch + 3) * Bstep);
            cpa_commit();
        }
        u32 af[2][4], qf[4][2], mf[4][2];
#pragma unroll
        for (int mi = 0; mi < 2; ++mi) {
            int m = mbase + mi * 16 + g;
            af[mi][0] = *(const u32*)&As[p][m][2 * t];
            af[mi][1] = *(const u32*)&As[p][m + 8][2 * t];
            af[mi][2] = *(const u32*)&As[p][m][2 * t + 8];
            af[mi][3] = *(const u32*)&As[p][m + 8][2 * t + 8];
        }
#pragma unroll
        for (int ni = 0; ni < 4; ++ni) {
            int n = nbase + ni * 8 + g;
            qf[ni][0] = *(const u32*)&Bq[p][t][2 * n];
            qf[ni][1] = *(const u32*)&Bq[p][t + 4][2 * n];
            mf[ni][0] = *(const u32*)&Bm[p][t][2 * n];
            mf[ni][1] = *(const u32*)&Bm[p][t + 4][2 * n];
        }
#pragma unroll
        for (int mi = 0; mi < 2; ++mi)
#pragma unroll
            for (int ni = 0; ni < 4; ++ni) {
                mma16(accA[mi][ni], af[mi][0], af[mi][1], af[mi][2], af[mi][3],
                      qf[ni][0], qf[ni][1]);
                mma16(accB[mi][ni], af[mi][0], af[mi][1], af[mi][2], af[mi][3],
                      mf[ni][0], mf[ni][1]);
            }
    }
#pragma unroll
    for (int mi = 0; mi < 2; ++mi) {
        int cA = c0 + mbase + mi * 16 + g;
        float i0 = 1.0f / g_rsum[b * LCc + cA];
        float i1 = 1.0f / g_rsum[b * LCc + cA + 8];
#pragma unroll
        for (int ni = 0; ni < 4; ++ni) {
            accA[mi][ni].x *= i0; accA[mi][ni].y *= i0;
            accA[mi][ni].z *= i1; accA[mi][ni].w *= i1;
            accB[mi][ni].x *= i0; accB[mi][ni].y *= i0;
            accB[mi][ni].z *= i1; accB[mi][ni].w *= i1;
        }
    }
    const int cl = tid & 63, dseg = (tid >> 6) * 16;
    const int cr = tid & 63, db = tid >> 6;
    const size_t ob = (size_t)b * (4 * ND) * LCc;
    for (int h = 0; h < 2; ++h) {
        __syncthreads();
        {
            const float* Cg = C + (size_t)(c0 + h * 64 + cl) * (NB * ND) + (size_t)b * ND + d0 + dseg;
#pragma unroll
            for (int dd = 0; dd < 16; dd += 4) {
                float4 cv = *(const float4*)(Cg + dd);
                Cs[dseg + dd + 0][cl] = cv.x; Cs[dseg + dd + 1][cl] = cv.y;
                Cs[dseg + dd + 2][cl] = cv.z; Cs[dseg + dd + 3][cl] = cv.w;
            }
        }
        if ((w >> 2) == h) {
#pragma unroll
            for (int mi = 0; mi < 2; ++mi) {
                int clh = (wr & 1) * 32 + mi * 16 + g;
#pragma unroll
                for (int ni = 0; ni < 4; ++ni) {
                    int d = nbase + ni * 8 + 2 * t;
                    Tr[clh][d] = accA[mi][ni].x;     Tr[clh][d + 1] = accA[mi][ni].y;
                    Tr[clh + 8][d] = accA[mi][ni].z; Tr[clh + 8][d + 1] = accA[mi][ni].w;
                }
            }
        }
        __syncthreads();
#pragma unroll
        for (int rr = 0; rr < 16; ++rr) {
            int dr = db + rr * 4;
            float cval = Cs[dr][cr];
            float aval = Tr[cr][dr];
            size_t col = (size_t)(c0 + h * 64 + cr);
            out[ob + (size_t)(d0 + dr) * LCc + col]          = cval;
            out[ob + (size_t)(ND + d0 + dr) * LCc + col]     = aval;
            out[ob + (size_t)(2 * ND + d0 + dr) * LCc + col] = cval * aval;
        }
        __syncthreads();
        if ((w >> 2) == h) {
#pragma unroll
            for (int mi = 0; mi < 2; ++mi) {
                int clh = (wr & 1) * 32 + mi * 16 + g;
#pragma unroll
                for (int ni = 0; ni < 4; ++ni) {
                    int d = nbase + ni * 8 + 2 * t;
                    Tr[clh][d] = accB[mi][ni].x;     Tr[clh][d + 1] = accB[mi][ni].y;
                    Tr[clh + 8][d] = accB[mi][ni].z; Tr[clh + 8][d + 1] = accB[mi][ni].w;
                }
            }
        }
        __syncthreads();
#pragma unroll
        for (int rr = 0; rr < 16; ++rr) {
            int dr = db + rr * 4;
            out[ob + (size_t)(3 * ND + d0 + dr) * LCc + (size_t)(c0 + h * 64 + cr)] =
                Cs[dr][cr] * Tr[cr][dr];
        }
    }
}

extern "C" void kernel_launch(void* const* d_in, const int* in_sizes, int n_in,
                              void* d_out, int out_size) {
    const float* C     = (const float*)d_in[0];
    const float* Q     = (const float*)d_in[1];
    const float* w4C   = (const float*)d_in[2];
    const float* w4Q   = (const float*)d_in[3];
    const float* w4mlu = (const float*)d_in[4];
    const float* bias  = (const float*)d_in[5];
    float* out = (float*)d_out;

    k_init<<<(NB * LCc + 255) / 256, 256>>>();
    k0_all<<<12288, 256>>>(C, Q, w4C, w4Q, w4mlu);
    k1_scores<<<dim3(LQq / 128, LCc / 128, NB), 256>>>(bias);
    k4_M<<<dim3(ND / 128, LQq / 128, NB), 256>>>();
    k5_out<<<dim3(ND / 64, LCc / 128, NB), 256>>>(C, out);
}

// round 15
// speedup vs baseline: 1.0814x; 1.0814x over previous
#include <cuda_runtime.h>
#include <cuda_fp16.h>
#include <math.h>

#define LCc 1024
#define LQq 512
#define NB  64
#define ND  256

typedef unsigned int u32;

__device__ __half g_Ch [(size_t)LCc * NB * ND];   // [c][b][d]            (k1 A)
__device__ __half g_C2 [(size_t)LCc * NB * ND];   // [c/2][b][d][c&1]     (k4 B)
__device__ __half g_Qwh[(size_t)LQq * NB * ND];   // [q][b][d]  Q*wml     (k1 B)
__device__ __half g_Q2 [(size_t)LQq * NB * ND];   // [q/2][b][d][q&1]     (k5 Bq)
__device__ __half g_Eh [(size_t)NB * LCc * LQq];  // [b][c][q]            (k5 A)
__device__ __half g_E2 [(size_t)NB * LCc * LQq];  // [b][c/2][q][c&1]     (k4 A)
__device__ __half g_M2 [(size_t)NB * LQq * ND];   // [b][q/2][d][q&1]     (k5 Bm)
__device__ float g_sub0[NB * LCc];
__device__ float g_sub1[NB * LQq];
__device__ float g_rsum[NB * LCc];
__device__ float g_csum2[NB * LQq];

// ---------------- helpers -----------------------------------------------------
__device__ __forceinline__ void mma16(float4& d,
        u32 a0, u32 a1, u32 a2, u32 a3, u32 b0, u32 b1) {
    asm volatile("mma.sync.aligned.m16n8k16.row.col.f32.f16.f16.f32 "
        "{%0,%1,%2,%3}, {%4,%5,%6,%7}, {%8,%9}, {%0,%1,%2,%3};"
        : "+f"(d.x), "+f"(d.y), "+f"(d.z), "+f"(d.w)
        : "r"(a0), "r"(a1), "r"(a2), "r"(a3), "r"(b0), "r"(b1));
}
__device__ __forceinline__ void ldsm_x4(u32& r0, u32& r1, u32& r2, u32& r3, u32 a) {
    asm volatile("ldmatrix.sync.aligned.m8n8.x4.shared.b16 {%0,%1,%2,%3}, [%4];"
        : "=r"(r0), "=r"(r1), "=r"(r2), "=r"(r3) : "r"(a));
}
__device__ __forceinline__ u32 smem_u32(const void* p) {
    u32 a; asm("{ .reg .u64 t; cvta.to.shared.u64 t, %1; cvt.u32.u64 %0, t; }"
               : "=r"(a) : "l"(p));
    return a;
}
__device__ __forceinline__ void cpa16(u32 dst, const void* src) {
    asm volatile("cp.async.cg.shared.global [%0], [%1], 16;" :: "r"(dst), "l"(src) : "memory");
}
__device__ __forceinline__ void cpa_commit() {
    asm volatile("cp.async.commit_group;" ::: "memory");
}
template<int N>
__device__ __forceinline__ void cpa_wait() {
    asm volatile("cp.async.wait_group %0;" :: "n"(N) : "memory");
}
__device__ __forceinline__ __half h_rn(float f) { return __float2half_rn(f); }
__device__ __forceinline__ float exp2p(float e) {
    float r = rintf(e);
    float f = e - r;
    float p = 1.33335581464e-3f;
    p = fmaf(p, f, 9.61812910763e-3f);
    p = fmaf(p, f, 5.55041086648e-2f);
    p = fmaf(p, f, 2.40226506959e-1f);
    p = fmaf(p, f, 6.93147180560e-1f);
    p = fmaf(p, f, 1.0f);
    int ei = (int)r;
    return p * __int_as_float((ei + 127) << 23);
}
#define L2E 1.44269504088896340736f

// ---------------- small kernels ------------------------------------------------
__global__ void k_init() {
    int i = blockIdx.x * blockDim.x + threadIdx.x;
    if (i < NB * LQq) { g_csum2[i] = 0.f; g_sub1[i] = 0.f; }
    if (i < NB * LCc) { g_rsum[i] = 0.f;  g_sub0[i] = 0.f; }
}

// ---- fused prepass: fp16 conversions + interleaved copies + sub0/sub1 dots ----
__global__ __launch_bounds__(256) void k0_all(const float* __restrict__ C,
                                              const float* __restrict__ Q,
                                              const float* __restrict__ w4C,
                                              const float* __restrict__ w4Q,
                                              const float* __restrict__ wml) {
    const int bid = blockIdx.x, tid = threadIdx.x;
    if (bid < 8192) {   // ---- C part ----
        int i = bid * 256 + tid;
        int d  = (i & 63) * 4;
        int b  = (i >> 6) & 63;
        int cp = i >> 12;
        float4 v0 = *(const float4*)(C + ((size_t)(2 * cp)     * NB + b) * ND + d);
        float4 v1 = *(const float4*)(C + ((size_t)(2 * cp + 1) * NB + b) * ND + d);
        __half2* c0 = (__half2*)(g_Ch + ((size_t)(2 * cp)     * NB + b) * ND + d);
        __half2* c1 = (__half2*)(g_Ch + ((size_t)(2 * cp + 1) * NB + b) * ND + d);
        c0[0] = __floats2half2_rn(v0.x, v0.y);
        c0[1] = __floats2half2_rn(v0.z, v0.w);
        c1[0] = __floats2half2_rn(v1.x, v1.y);
        c1[1] = __floats2half2_rn(v1.z, v1.w);
        __half2* c2 = (__half2*)(g_C2 + (((size_t)cp * NB + b) * ND + d) * 2);
        c2[0] = __floats2half2_rn(v0.x, v1.x);
        c2[1] = __floats2half2_rn(v0.y, v1.y);
        c2[2] = __floats2half2_rn(v0.z, v1.z);
        c2[3] = __floats2half2_rn(v0.w, v1.w);
        float4 wc = *(const float4*)(w4C + d);
        float d0 = v0.x * wc.x + v0.y * wc.y + v0.z * wc.z + v0.w * wc.w;
        float d1 = v1.x * wc.x + v1.y * wc.y + v1.z * wc.z + v1.w * wc.w;
#pragma unroll
        for (int off = 16; off; off >>= 1) {
            d0 += __shfl_xor_sync(0xffffffffu, d0, off);
            d1 += __shfl_xor_sync(0xffffffffu, d1, off);
        }
        if ((tid & 31) == 0) {
            atomicAdd(&g_sub0[b * LCc + 2 * cp], d0);
            atomicAdd(&g_sub0[b * LCc + 2 * cp + 1], d1);
        }
    } else {            // ---- Q part ----
        int i = (bid - 8192) * 256 + tid;
        int d  = (i & 63) * 4;
        int b  = (i >> 6) & 63;
        int qp = i >> 12;
        float4 ww = ((const float4*)wml)[i & 63];
        float4 v0 = *(const float4*)(Q + ((size_t)(2 * qp)     * NB + b) * ND + d);
        float4 v1 = *(const float4*)(Q + ((size_t)(2 * qp + 1) * NB + b) * ND + d);
        __half2* w0 = (__half2*)(g_Qwh + ((size_t)(2 * qp)     * NB + b) * ND + d);
        __half2* w1 = (__half2*)(g_Qwh + ((size_t)(2 * qp + 1) * NB + b) * ND + d);
        w0[0] = __floats2half2_rn(v0.x * ww.x, v0.y * ww.y);
        w0[1] = __floats2half2_rn(v0.z * ww.z, v0.w * ww.w);
        w1[0] = __floats2half2_rn(v1.x * ww.x, v1.y * ww.y);
        w1[1] = __floats2half2_rn(v1.z * ww.z, v1.w * ww.w);
        __half2* q2 = (__half2*)(g_Q2 + (((size_t)qp * NB + b) * ND + d) * 2);
        q2[0] = __floats2half2_rn(v0.x, v1.x);
        q2[1] = __floats2half2_rn(v0.y, v1.y);
        q2[2] = __floats2half2_rn(v0.z, v1.z);
        q2[3] = __floats2half2_rn(v0.w, v1.w);
        float4 wq = *(const float4*)(w4Q + d);
        float d0 = v0.x * wq.x + v0.y * wq.y + v0.z * wq.z + v0.w * wq.w;
        float d1 = v1.x * wq.x + v1.y * wq.y + v1.z * wq.z + v1.w * wq.w;
#pragma unroll
        for (int off = 16; off; off >>= 1) {
            d0 += __shfl_xor_sync(0xffffffffu, d0, off);
            d1 += __shfl_xor_sync(0xffffffffu, d1, off);
        }
        if ((tid & 31) == 0) {
            atomicAdd(&g_sub1[b * LQq + 2 * qp], d0);
            atomicAdd(&g_sub1[b * LQq + 2 * qp + 1], d1);
        }
    }
}

// ---- k1: E = exp(Ch @ Qwh^T + sub0 + sub1 + bias); ldmatrix fragments ---------
__global__ __launch_bounds__(256, 2) void k1_scores(const float* __restrict__ bias) {
    __shared__ __half As[2][128][40];
    __shared__ __half Bs[2][128][40];
    const int tid = threadIdx.x, lane = tid & 31, w = tid >> 5;
    const int g = lane >> 2, t = lane & 3;
    const int b = blockIdx.z, c0 = blockIdx.y * 128, q0 = blockIdx.x * 128;
    const int mbase = (w >> 2) * 64, nbase = (w & 3) * 32;
    const int row = tid >> 1, sg = (tid & 1) * 16;
    const __half* Ag = g_Ch + ((size_t)(c0 + row) * NB + b) * ND + sg;
    const __half* Bg = g_Qwh + ((size_t)(q0 + row) * NB + b) * ND + sg;
    const u32 Ad = smem_u32(&As[0][row][sg]);
    const u32 Bd = smem_u32(&Bs[0][row][sg]);
    // ldmatrix lane address components
    const int arow = lane & 15, akoff = (lane >> 4) * 8;
    const int brow = ((lane >> 4) << 3) + (lane & 7), bkoff = ((lane >> 3) & 1) * 8;
    const u32 A0 = smem_u32(&As[0][0][0]);
    const u32 B0 = smem_u32(&Bs[0][0][0]);
    cpa16(Ad, Ag); cpa16(Ad + 16, Ag + 8);
    cpa16(Bd, Bg); cpa16(Bd + 16, Bg + 8);
    cpa_commit();
    float4 acc[4][4] = {};
    for (int ch = 0; ch < 8; ++ch) {
        const int p = ch & 1;
        if (ch < 7) {
            const int ko = (ch + 1) * 32;
            const u32 off = (u32)((p ^ 1) * 10240);
            cpa16(Ad + off, Ag + ko); cpa16(Ad + off + 16, Ag + ko + 8);
            cpa16(Bd + off, Bg + ko); cpa16(Bd + off + 16, Bg + ko + 8);
            cpa_commit();
            cpa_wait<1>();
        } else cpa_wait<0>();
        __syncthreads();
#pragma unroll
        for (int kk = 0; kk < 32; kk += 16) {
            u32 af[4][4], bf[4][2];
            u32 abase = A0 + (u32)p * 10240 + (u32)((mbase + arow) * 80 + (kk + akoff) * 2);
            u32 bbase = B0 + (u32)p * 10240 + (u32)((nbase + brow) * 80 + (kk + bkoff) * 2);
#pragma unroll
            for (int mi = 0; mi < 4; ++mi)
                ldsm_x4(af[mi][0], af[mi][1], af[mi][2], af[mi][3], abase + mi * 16 * 80);
#pragma unroll
            for (int nj = 0; nj < 2; ++nj)
                ldsm_x4(bf[2 * nj][0], bf[2 * nj][1], bf[2 * nj + 1][0], bf[2 * nj + 1][1],
                        bbase + nj * 16 * 80);
#pragma unroll
            for (int mi = 0; mi < 4; ++mi)
#pragma unroll
                for (int ni = 0; ni < 4; ++ni)
                    mma16(acc[mi][ni], af[mi][0], af[mi][1], af[mi][2], af[mi][3],
                          bf[ni][0], bf[ni][1]);
        }
        __syncthreads();
    }
    const float bv = bias[0];
    float s1x[4], s1y[4];
#pragma unroll
    for (int ni = 0; ni < 4; ++ni) {
        int q = q0 + nbase + ni * 8 + 2 * t;
        s1x[ni] = g_sub1[b * LQq + q] * L2E;
        s1y[ni] = g_sub1[b * LQq + q + 1] * L2E;
    }
    float rs0[4] = {}, rs1[4] = {}, ccx[4] = {}, ccy[4] = {};
#pragma unroll
    for (int mi = 0; mi < 4; ++mi) {
        int cA = c0 + mbase + mi * 16 + g;
        float s0a = (g_sub0[b * LCc + cA] + bv) * L2E;
        float s0b = (g_sub0[b * LCc + cA + 8] + bv) * L2E;
        __half* r0 = g_Eh + (size_t)(b * LCc + cA) * LQq + q0;
        __half* r1 = r0 + (size_t)8 * LQq;
        size_t e20 = ((size_t)(b * (LCc / 2) + (cA >> 1)) * LQq + q0) * 2 + (cA & 1);
        size_t e21 = e20 + (size_t)8 * LQq;
#pragma unroll
        for (int ni = 0; ni < 4; ++ni) {
            int q = nbase + ni * 8 + 2 * t;
            float f00 = exp2p(fmaf(acc[mi][ni].x, L2E, s0a + s1x[ni]));
            float f01 = exp2p(fmaf(acc[mi][ni].y, L2E, s0a + s1y[ni]));
            float f10 = exp2p(fmaf(acc[mi][ni].z, L2E, s0b + s1x[ni]));
            float f11 = exp2p(fmaf(acc[mi][ni].w, L2E, s0b + s1y[ni]));
            __half h00 = h_rn(f00), h01 = h_rn(f01);
            __half h10 = h_rn(f10), h11 = h_rn(f11);
            *(__half2*)(r0 + q) = __halves2half2(h00, h01);
            *(__half2*)(r1 + q) = __halves2half2(h10, h11);
            g_E2[e20 + 2 * q] = h00; g_E2[e20 + 2 * q + 2] = h01;
            g_E2[e21 + 2 * q] = h10; g_E2[e21 + 2 * q + 2] = h11;
            float v00 = __half2float(h00), v01 = __half2float(h01);
            float v10 = __half2float(h10), v11 = __half2float(h11);
            rs0[mi] += v00 + v01; rs1[mi] += v10 + v11;
            ccx[ni] += v00 + v10; ccy[ni] += v01 + v11;
        }
    }
#pragma unroll
    for (int mi = 0; mi < 4; ++mi) {
        float a = rs0[mi], c2 = rs1[mi];
        a  += __shfl_xor_sync(0xffffffffu, a, 1);  a  += __shfl_xor_sync(0xffffffffu, a, 2);
        c2 += __shfl_xor_sync(0xffffffffu, c2, 1); c2 += __shfl_xor_sync(0xffffffffu, c2, 2);
        if (t == 0) {
            int cA = c0 + mbase + mi * 16 + g;
            atomicAdd(&g_rsum[b * LCc + cA], a);
            atomicAdd(&g_rsum[b * LCc + cA + 8], c2);
        }
    }
#pragma unroll
    for (int ni = 0; ni < 4; ++ni) {
        float x = ccx[ni], y = ccy[ni];
        x += __shfl_xor_sync(0xffffffffu, x, 4);  y += __shfl_xor_sync(0xffffffffu, y, 4);
        x += __shfl_xor_sync(0xffffffffu, x, 8);  y += __shfl_xor_sync(0xffffffffu, y, 8);
        x += __shfl_xor_sync(0xffffffffu, x, 16); y += __shfl_xor_sync(0xffffffffu, y, 16);
        if (g == 0) {
            int q = q0 + nbase + ni * 8 + 2 * t;
            atomicAdd(&g_csum2[b * LQq + q], x);
            atomicAdd(&g_csum2[b * LQq + q + 1], y);
        }
    }
}

// ---- k4: M2 = (E^T @ C / colsum); A=g_E2, B=g_C2 (R13 double-buffer) -----------
__global__ __launch_bounds__(256, 2) void k4_M() {
    __shared__ __half As[2][16][272];
    __shared__ __half Bs[2][16][272];
    const int b = blockIdx.z, q0 = blockIdx.y * 128, d0 = blockIdx.x * 128;
    const int tid = threadIdx.x, lane = tid & 31, w = tid >> 5;
    const int g = lane >> 2, t = lane & 3;
    const int mbase = (w >> 2) * 64, nbase = (w & 3) * 32;
    const int k2r = tid >> 4, sg = (tid & 15) * 16;
    const __half* Ag = g_E2 + ((size_t)(b * (LCc / 2) + k2r) * LQq + q0) * 2 + sg;
    const __half* Bg = g_C2 + ((size_t)(k2r * NB + b) * ND + d0) * 2 + sg;
    const u32 Ad = smem_u32(&As[0][k2r][sg]);
    const u32 Bd = smem_u32(&Bs[0][k2r][sg]);
    cpa16(Ad, Ag); cpa16(Ad + 16, Ag + 8);
    cpa16(Bd, Bg); cpa16(Bd + 16, Bg + 8);
    cpa_commit();
    float4 acc[4][4] = {};
    for (int ch = 0; ch < 32; ++ch) {
        const int p = ch & 1;
        if (ch < 31) {
            const size_t ca = (size_t)(ch + 1) * 16;
            const u32 off = (u32)((p ^ 1) * 8704);
            cpa16(Ad + off, Ag + ca * (LQq * 2));
            cpa16(Ad + off + 16, Ag + ca * (LQq * 2) + 8);
            cpa16(Bd + off, Bg + ca * ((size_t)NB * ND * 2));
            cpa16(Bd + off + 16, Bg + ca * ((size_t)NB * ND * 2) + 8);
            cpa_commit();
            cpa_wait<1>();
        } else cpa_wait<0>();
        __syncthreads();
#pragma unroll
        for (int s = 0; s < 2; ++s) {
            u32 af[4][4], bf[4][2];
#pragma unroll
            for (int mi = 0; mi < 4; ++mi) {
                int m = mbase + mi * 16 + g;
                af[mi][0] = *(const u32*)&As[p][8 * s + t][2 * m];
                af[mi][1] = *(const u32*)&As[p][8 * s + t][2 * (m + 8)];
                af[mi][2] = *(const u32*)&As[p][8 * s + t + 4][2 * m];
                af[mi][3] = *(const u32*)&As[p][8 * s + t + 4][2 * (m + 8)];
            }
#pragma unroll
            for (int ni = 0; ni < 4; ++ni) {
                int n = nbase + ni * 8 + g;
                bf[ni][0] = *(const u32*)&Bs[p][8 * s + t][2 * n];
                bf[ni][1] = *(const u32*)&Bs[p][8 * s + t + 4][2 * n];
            }
#pragma unroll
            for (int mi = 0; mi < 4; ++mi)
#pragma unroll
                for (int ni = 0; ni < 4; ++ni)
                    mma16(acc[mi][ni], af[mi][0], af[mi][1], af[mi][2], af[mi][3],
                          bf[ni][0], bf[ni][1]);
        }
        __syncthreads();
    }
#pragma unroll
    for (int mi = 0; mi < 4; ++mi) {
        int qA = q0 + mbase + mi * 16 + g;
        float i0 = 1.0f / g_csum2[b * LQq + qA];
        float i1 = 1.0f / g_csum2[b * LQq + qA + 8];
        size_t m0b = ((size_t)(b * (LQq / 2) + (qA >> 1)) * ND + d0) * 2 + (qA & 1);
        size_t m1b = m0b + (size_t)8 * ND;
#pragma unroll
        for (int ni = 0; ni < 4; ++ni) {
            int d = nbase + ni * 8 + 2 * t;
            g_M2[m0b + 2 * d]     = h_rn(acc[mi][ni].x * i0);
            g_M2[m0b + 2 * d + 2] = h_rn(acc[mi][ni].y * i0);
            g_M2[m1b + 2 * d]     = h_rn(acc[mi][ni].z * i1);
            g_M2[m1b + 2 * d + 2] = h_rn(acc[mi][ni].w * i1);
        }
    }
}

// ---- k5: A = S1@Q, B_ = S1@M (R13 double-buffer); transposed concat ------------
__global__ __launch_bounds__(256, 2) void k5_out(const float* __restrict__ C,
                                                 float* __restrict__ out) {
    __shared__ __align__(16) char sm5[38912];
    __half (*As)[128][40] = (__half(*)[128][40])sm5;              // 2*10240
    __half (*Bq)[16][144] = (__half(*)[16][144])(sm5 + 20480);    // 2*4608
    __half (*Bm)[16][144] = (__half(*)[16][144])(sm5 + 29696);    // 2*4608
    float (*Cs)[65]       = (float(*)[65])sm5;                    // epilogue
    float (*Tr)[69]       = (float(*)[69])(sm5 + 16640);          // epilogue
    const int b = blockIdx.z, c0 = blockIdx.y * 128, d0 = blockIdx.x * 64;
    const int tid = threadIdx.x, lane = tid & 31, w = tid >> 5;
    const int g = lane >> 2, t = lane & 3;
    const int wr = w >> 1, wc = w & 1;
    const int mbase = wr * 32, nbase = wc * 32;
    const int rowc = tid >> 1, sgA = (tid & 1) * 16;
    const int k2r = tid >> 4, sgB = (tid & 15) * 8;
    const __half* Ag = g_Eh + (size_t)(b * LCc + c0 + rowc) * LQq + sgA;
    const __half* Qg = g_Q2 + ((size_t)(k2r * NB + b) * ND + d0) * 2 + sgB;
    const __half* Mg = g_M2 + ((size_t)(b * (LQq / 2) + k2r) * ND + d0) * 2 + sgB;
    const u32 Ad  = smem_u32(&As[0][rowc][sgA]);
    const u32 Bqd = smem_u32(&Bq[0][k2r][sgB]);
    const u32 Bmd = smem_u32(&Bm[0][k2r][sgB]);
    cpa16(Ad, Ag); cpa16(Ad + 16, Ag + 8);
    cpa16(Bqd, Qg); cpa16(Bmd, Mg);
    cpa_commit();
    float4 accA[2][4] = {}, accB[2][4] = {};
    for (int ch = 0; ch < 16; ++ch) {
        const int p = ch & 1;
        if (ch < 15) {
            const int ko = (ch + 1) * 32;
            const u32 offA = (u32)((p ^ 1) * 10240);
            const u32 offB = (u32)((p ^ 1) * 4608);
            cpa16(Ad + offA, Ag + ko); cpa16(Ad + offA + 16, Ag + ko + 8);
            cpa16(Bqd + offB, Qg + (size_t)(ch + 1) * 16 * ((size_t)NB * ND * 2));
            cpa16(Bmd + offB, Mg + (size_t)(ch + 1) * 16 * (ND * 2));
            cpa_commit();
            cpa_wait<1>();
        } else cpa_wait<0>();
        __syncthreads();
#pragma unroll
        for (int s = 0; s < 2; ++s) {
            u32 af[2][4], qf[4][2], mf[4][2];
#pragma unroll
            for (int mi = 0; mi < 2; ++mi) {
                int m = mbase + mi * 16 + g;
                af[mi][0] = *(const u32*)&As[p][m][16 * s + 2 * t];
                af[mi][1] = *(const u32*)&As[p][m + 8][16 * s + 2 * t];
                af[mi][2] = *(const u32*)&As[p][m][16 * s + 2 * t + 8];
                af[mi][3] = *(const u32*)&As[p][m + 8][16 * s + 2 * t + 8];
            }
#pragma unroll
            for (int ni = 0; ni < 4; ++ni) {
                int n = nbase + ni * 8 + g;
                qf[ni][0] = *(const u32*)&Bq[p][8 * s + t][2 * n];
                qf[ni][1] = *(const u32*)&Bq[p][8 * s + t + 4][2 * n];
                mf[ni][0] = *(const u32*)&Bm[p][8 * s + t][2 * n];
                mf[ni][1] = *(const u32*)&Bm[p][8 * s + t + 4][2 * n];
            }
#pragma unroll
            for (int mi = 0; mi < 2; ++mi)
#pragma unroll
                for (int ni = 0; ni < 4; ++ni) {
                    mma16(accA[mi][ni], af[mi][0], af[mi][1], af[mi][2], af[mi][3],
                          qf[ni][0], qf[ni][1]);
                    mma16(accB[mi][ni], af[mi][0], af[mi][1], af[mi][2], af[mi][3],
                          mf[ni][0], mf[ni][1]);
                }
        }
        __syncthreads();
    }
#pragma unroll
    for (int mi = 0; mi < 2; ++mi) {
        int cA = c0 + mbase + mi * 16 + g;
        float i0 = 1.0f / g_rsum[b * LCc + cA];
        float i1 = 1.0f / g_rsum[b * LCc + cA + 8];
#pragma unroll
        for (int ni = 0; ni < 4; ++ni) {
            accA[mi][ni].x *= i0; accA[mi][ni].y *= i0;
            accA[mi][ni].z *= i1; accA[mi][ni].w *= i1;
            accB[mi][ni].x *= i0; accB[mi][ni].y *= i0;
            accB[mi][ni].z *= i1; accB[mi][ni].w *= i1;
        }
    }
    const int cl = tid & 63, dseg = (tid >> 6) * 16;
    const int cr = tid & 63, db = tid >> 6;
    const size_t ob = (size_t)b * (4 * ND) * LCc;
    for (int h = 0; h < 2; ++h) {
        __syncthreads();
        {
            const float* Cg = C + (size_t)(c0 + h * 64 + cl) * (NB * ND) + (size_t)b * ND + d0 + dseg;
#pragma unroll
            for (int dd = 0; dd < 16; dd += 4) {
                float4 cv = *(const float4*)(Cg + dd);
                Cs[dseg + dd + 0][cl] = cv.x; Cs[dseg + dd + 1][cl] = cv.y;
                Cs[dseg + dd + 2][cl] = cv.z; Cs[dseg + dd + 3][cl] = cv.w;
            }
        }
        if ((w >> 2) == h) {
#pragma unroll
            for (int mi = 0; mi < 2; ++mi) {
                int clh = (wr & 1) * 32 + mi * 16 + g;
#pragma unroll
                for (int ni = 0; ni < 4; ++ni) {
                    int d = nbase + ni * 8 + 2 * t;
                    Tr[clh][d] = accA[mi][ni].x;     Tr[clh][d + 1] = accA[mi][ni].y;
                    Tr[clh + 8][d] = accA[mi][ni].z; Tr[clh + 8][d + 1] = accA[mi][ni].w;
                }
            }
        }
        __syncthreads();
#pragma unroll
        for (int rr = 0; rr < 16; ++rr) {
            int dr = db + rr * 4;
            float cval = Cs[dr][cr];
            float aval = Tr[cr][dr];
            size_t col = (size_t)(c0 + h * 64 + cr);
            out[ob + (size_t)(d0 + dr) * LCc + col]          = cval;
            out[ob + (size_t)(ND + d0 + dr) * LCc + col]     = aval;
            out[ob + (size_t)(2 * ND + d0 + dr) * LCc + col] = cval * aval;
        }
        __syncthreads();
        if ((w >> 2) == h) {
#pragma unroll
            for (int mi = 0; mi < 2; ++mi) {
                int clh = (wr & 1) * 32 + mi * 16 + g;
#pragma unroll
                for (int ni = 0; ni < 4; ++ni) {
                    int d = nbase + ni * 8 + 2 * t;
                    Tr[clh][d] = accB[mi][ni].x;     Tr[clh][d + 1] = accB[mi][ni].y;
                    Tr[clh + 8][d] = accB[mi][ni].z; Tr[clh + 8][d + 1] = accB[mi][ni].w;
                }
            }
        }
        __syncthreads();
#pragma unroll
        for (int rr = 0; rr < 16; ++rr) {
            int dr = db + rr * 4;
            out[ob + (size_t)(3 * ND + d0 + dr) * LCc + (size_t)(c0 + h * 64 + cr)] =
                Cs[dr][cr] * Tr[cr][dr];
        }
    }
}

extern "C" void kernel_launch(void* const* d_in, const int* in_sizes, int n_in,
                              void* d_out, int out_size) {
    const float* C     = (const float*)d_in[0];
    const float* Q     = (const float*)d_in[1];
    const float* w4C   = (const float*)d_in[2];
    const float* w4Q   = (const float*)d_in[3];
    const float* w4mlu = (const float*)d_in[4];
    const float* bias  = (const float*)d_in[5];
    float* out = (float*)d_out;

    k_init<<<(NB * LCc + 255) / 256, 256>>>();
    k0_all<<<12288, 256>>>(C, Q, w4C, w4Q, w4mlu);
    k1_scores<<<dim3(LQq / 128, LCc / 128, NB), 256>>>(bias);
    k4_M<<<dim3(ND / 128, LQq / 128, NB), 256>>>();
    k5_out<<<dim3(ND / 64, LCc / 128, NB), 256>>>(C, out);
}

// round 17
// speedup vs baseline: 1.1709x; 1.0828x over previous
#include <cuda_runtime.h>
#include <cuda_fp16.h>
#include <math.h>

#define LCc 1024
#define LQq 512
#define NB  64
#define ND  256

typedef unsigned int u32;

__device__ __half g_Ch [(size_t)LCc * NB * ND];   // [c][b][d]            (k1 A, k4 B)
__device__ __half g_Qwh[(size_t)LQq * NB * ND];   // [q][b][d]  Q*wml     (k1 B)
__device__ __half g_Q2 [(size_t)LQq * NB * ND];   // [q/2][b][d][q&1]     (k5 Bq)
__device__ __half g_Eh [(size_t)NB * LCc * LQq];  // [b][c][q]            (k4 A, k5 A)
__device__ __half g_M2 [(size_t)NB * LQq * ND];   // [b][q/2][d][q&1]     (k5 Bm)
__device__ float g_sub0[NB * LCc];
__device__ float g_sub1[NB * LQq];
__device__ float g_rsum[NB * LCc];
__device__ float g_csum2[NB * LQq];

// ---------------- helpers -----------------------------------------------------
__device__ __forceinline__ void mma16(float4& d,
        u32 a0, u32 a1, u32 a2, u32 a3, u32 b0, u32 b1) {
    asm volatile("mma.sync.aligned.m16n8k16.row.col.f32.f16.f16.f32 "
        "{%0,%1,%2,%3}, {%4,%5,%6,%7}, {%8,%9}, {%0,%1,%2,%3};"
        : "+f"(d.x), "+f"(d.y), "+f"(d.z), "+f"(d.w)
        : "r"(a0), "r"(a1), "r"(a2), "r"(a3), "r"(b0), "r"(b1));
}
__device__ __forceinline__ void ldsm_x4(u32& r0, u32& r1, u32& r2, u32& r3, u32 a) {
    asm volatile("ldmatrix.sync.aligned.m8n8.x4.shared.b16 {%0,%1,%2,%3}, [%4];"
        : "=r"(r0), "=r"(r1), "=r"(r2), "=r"(r3) : "r"(a));
}
__device__ __forceinline__ void ldsm_x4t(u32& r0, u32& r1, u32& r2, u32& r3, u32 a) {
    asm volatile("ldmatrix.sync.aligned.m8n8.x4.trans.shared.b16 {%0,%1,%2,%3}, [%4];"
        : "=r"(r0), "=r"(r1), "=r"(r2), "=r"(r3) : "r"(a));
}
__device__ __forceinline__ u32 smem_u32(const void* p) {
    u32 a; asm("{ .reg .u64 t; cvta.to.shared.u64 t, %1; cvt.u32.u64 %0, t; }"
               : "=r"(a) : "l"(p));
    return a;
}
__device__ __forceinline__ void cpa16(u32 dst, const void* src) {
    asm volatile("cp.async.cg.shared.global [%0], [%1], 16;" :: "r"(dst), "l"(src) : "memory");
}
__device__ __forceinline__ void cpa_commit() {
    asm volatile("cp.async.commit_group;" ::: "memory");
}
template<int N>
__device__ __forceinline__ void cpa_wait() {
    asm volatile("cp.async.wait_group %0;" :: "n"(N) : "memory");
}
__device__ __forceinline__ __half h_rn(float f) { return __float2half_rn(f); }
__device__ __forceinline__ float exp2p(float e) {
    float r = rintf(e);
    float f = e - r;
    float p = 1.33335581464e-3f;
    p = fmaf(p, f, 9.61812910763e-3f);
    p = fmaf(p, f, 5.55041086648e-2f);
    p = fmaf(p, f, 2.40226506959e-1f);
    p = fmaf(p, f, 6.93147180560e-1f);
    p = fmaf(p, f, 1.0f);
    int ei = (int)r;
    return p * __int_as_float((ei + 127) << 23);
}
#define L2E 1.44269504088896340736f

// ---------------- small kernels ------------------------------------------------
__global__ void k_init() {
    int i = blockIdx.x * blockDim.x + threadIdx.x;
    if (i < NB * LQq) { g_csum2[i] = 0.f; g_sub1[i] = 0.f; }
    if (i < NB * LCc) { g_rsum[i] = 0.f;  g_sub0[i] = 0.f; }
}

// ---- fused prepass: fp16 conversions + interleaved copies + sub0/sub1 dots ----
__global__ __launch_bounds__(256) void k0_all(const float* __restrict__ C,
                                              const float* __restrict__ Q,
                                              const float* __restrict__ w4C,
                                              const float* __restrict__ w4Q,
                                              const float* __restrict__ wml) {
    const int bid = blockIdx.x, tid = threadIdx.x;
    if (bid < 8192) {   // ---- C part ----
        int i = bid * 256 + tid;
        int d  = (i & 63) * 4;
        int b  = (i >> 6) & 63;
        int cp = i >> 12;
        float4 v0 = *(const float4*)(C + ((size_t)(2 * cp)     * NB + b) * ND + d);
        float4 v1 = *(const float4*)(C + ((size_t)(2 * cp + 1) * NB + b) * ND + d);
        __half2* c0 = (__half2*)(g_Ch + ((size_t)(2 * cp)     * NB + b) * ND + d);
        __half2* c1 = (__half2*)(g_Ch + ((size_t)(2 * cp + 1) * NB + b) * ND + d);
        c0[0] = __floats2half2_rn(v0.x, v0.y);
        c0[1] = __floats2half2_rn(v0.z, v0.w);
        c1[0] = __floats2half2_rn(v1.x, v1.y);
        c1[1] = __floats2half2_rn(v1.z, v1.w);
        float4 wc = *(const float4*)(w4C + d);
        float d0 = v0.x * wc.x + v0.y * wc.y + v0.z * wc.z + v0.w * wc.w;
        float d1 = v1.x * wc.x + v1.y * wc.y + v1.z * wc.z + v1.w * wc.w;
#pragma unroll
        for (int off = 16; off; off >>= 1) {
            d0 += __shfl_xor_sync(0xffffffffu, d0, off);
            d1 += __shfl_xor_sync(0xffffffffu, d1, off);
        }
        if ((tid & 31) == 0) {
            atomicAdd(&g_sub0[b * LCc + 2 * cp], d0);
            atomicAdd(&g_sub0[b * LCc + 2 * cp + 1], d1);
        }
    } else {            // ---- Q part ----
        int i = (bid - 8192) * 256 + tid;
        int d  = (i & 63) * 4;
        int b  = (i >> 6) & 63;
        int qp = i >> 12;
        float4 ww = ((const float4*)wml)[i & 63];
        float4 v0 = *(const float4*)(Q + ((size_t)(2 * qp)     * NB + b) * ND + d);
        float4 v1 = *(const float4*)(Q + ((size_t)(2 * qp + 1) * NB + b) * ND + d);
        __half2* w0 = (__half2*)(g_Qwh + ((size_t)(2 * qp)     * NB + b) * ND + d);
        __half2* w1 = (__half2*)(g_Qwh + ((size_t)(2 * qp + 1) * NB + b) * ND + d);
        w0[0] = __floats2half2_rn(v0.x * ww.x, v0.y * ww.y);
        w0[1] = __floats2half2_rn(v0.z * ww.z, v0.w * ww.w);
        w1[0] = __floats2half2_rn(v1.x * ww.x, v1.y * ww.y);
        w1[1] = __floats2half2_rn(v1.z * ww.z, v1.w * ww.w);
        __half2* q2 = (__half2*)(g_Q2 + (((size_t)qp * NB + b) * ND + d) * 2);
        q2[0] = __floats2half2_rn(v0.x, v1.x);
        q2[1] = __floats2half2_rn(v0.y, v1.y);
        q2[2] = __floats2half2_rn(v0.z, v1.z);
        q2[3] = __floats2half2_rn(v0.w, v1.w);
        float4 wq = *(const float4*)(w4Q + d);
        float d0 = v0.x * wq.x + v0.y * wq.y + v0.z * wq.z + v0.w * wq.w;
        float d1 = v1.x * wq.x + v1.y * wq.y + v1.z * wq.z + v1.w * wq.w;
#pragma unroll
        for (int off = 16; off; off >>= 1) {
            d0 += __shfl_xor_sync(0xffffffffu, d0, off);
            d1 += __shfl_xor_sync(0xffffffffu, d1, off);
        }
        if ((tid & 31) == 0) {
            atomicAdd(&g_sub1[b * LQq + 2 * qp], d0);
            atomicAdd(&g_sub1[b * LQq + 2 * qp + 1], d1);
        }
    }
}

// ---- k1: E = exp(Ch @ Qwh^T + sub0 + sub1 + bias); ldmatrix fragments ---------
__global__ __launch_bounds__(256, 2) void k1_scores(const float* __restrict__ bias) {
    __shared__ __half As[2][128][40];
    __shared__ __half Bs[2][128][40];
    const int tid = threadIdx.x, lane = tid & 31, w = tid >> 5;
    const int g = lane >> 2, t = lane & 3;
    const int b = blockIdx.z, c0 = blockIdx.y * 128, q0 = blockIdx.x * 128;
    const int mbase = (w >> 2) * 64, nbase = (w & 3) * 32;
    const int row = tid >> 1, sg = (tid & 1) * 16;
    const __half* Ag = g_Ch + ((size_t)(c0 + row) * NB + b) * ND + sg;
    const __half* Bg = g_Qwh + ((size_t)(q0 + row) * NB + b) * ND + sg;
    const u32 Ad = smem_u32(&As[0][row][sg]);
    const u32 Bd = smem_u32(&Bs[0][row][sg]);
    const int arow = lane & 15, akoff = (lane >> 4) * 8;
    const int brow = ((lane >> 4) << 3) + (lane & 7), bkoff = ((lane >> 3) & 1) * 8;
    const u32 A0 = smem_u32(&As[0][0][0]);
    const u32 B0 = smem_u32(&Bs[0][0][0]);
    cpa16(Ad, Ag); cpa16(Ad + 16, Ag + 8);
    cpa16(Bd, Bg); cpa16(Bd + 16, Bg + 8);
    cpa_commit();
    float4 acc[4][4] = {};
    for (int ch = 0; ch < 8; ++ch) {
        const int p = ch & 1;
        if (ch < 7) {
            const int ko = (ch + 1) * 32;
            const u32 off = (u32)((p ^ 1) * 10240);
            cpa16(Ad + off, Ag + ko); cpa16(Ad + off + 16, Ag + ko + 8);
            cpa16(Bd + off, Bg + ko); cpa16(Bd + off + 16, Bg + ko + 8);
            cpa_commit();
            cpa_wait<1>();
        } else cpa_wait<0>();
        __syncthreads();
#pragma unroll
        for (int kk = 0; kk < 32; kk += 16) {
            u32 af[4][4], bf[4][2];
            u32 abase = A0 + (u32)p * 10240 + (u32)((mbase + arow) * 80 + (kk + akoff) * 2);
            u32 bbase = B0 + (u32)p * 10240 + (u32)((nbase + brow) * 80 + (kk + bkoff) * 2);
#pragma unroll
            for (int mi = 0; mi < 4; ++mi)
                ldsm_x4(af[mi][0], af[mi][1], af[mi][2], af[mi][3], abase + mi * 16 * 80);
#pragma unroll
            for (int nj = 0; nj < 2; ++nj)
                ldsm_x4(bf[2 * nj][0], bf[2 * nj][1], bf[2 * nj + 1][0], bf[2 * nj + 1][1],
                        bbase + nj * 16 * 80);
#pragma unroll
            for (int mi = 0; mi < 4; ++mi)
#pragma unroll
                for (int ni = 0; ni < 4; ++ni)
                    mma16(acc[mi][ni], af[mi][0], af[mi][1], af[mi][2], af[mi][3],
                          bf[ni][0], bf[ni][1]);
        }
        __syncthreads();
    }
    const float bv = bias[0];
    float s1x[4], s1y[4];
#pragma unroll
    for (int ni = 0; ni < 4; ++ni) {
        int q = q0 + nbase + ni * 8 + 2 * t;
        s1x[ni] = g_sub1[b * LQq + q] * L2E;
        s1y[ni] = g_sub1[b * LQq + q + 1] * L2E;
    }
    float rs0[4] = {}, rs1[4] = {}, ccx[4] = {}, ccy[4] = {};
#pragma unroll
    for (int mi = 0; mi < 4; ++mi) {
        int cA = c0 + mbase + mi * 16 + g;
        float s0a = (g_sub0[b * LCc + cA] + bv) * L2E;
        float s0b = (g_sub0[b * LCc + cA + 8] + bv) * L2E;
        __half* r0 = g_Eh + (size_t)(b * LCc + cA) * LQq + q0;
        __half* r1 = r0 + (size_t)8 * LQq;
#pragma unroll
        for (int ni = 0; ni < 4; ++ni) {
            int q = nbase + ni * 8 + 2 * t;
            float f00 = exp2p(fmaf(acc[mi][ni].x, L2E, s0a + s1x[ni]));
            float f01 = exp2p(fmaf(acc[mi][ni].y, L2E, s0a + s1y[ni]));
            float f10 = exp2p(fmaf(acc[mi][ni].z, L2E, s0b + s1x[ni]));
            float f11 = exp2p(fmaf(acc[mi][ni].w, L2E, s0b + s1y[ni]));
            __half h00 = h_rn(f00), h01 = h_rn(f01);
            __half h10 = h_rn(f10), h11 = h_rn(f11);
            *(__half2*)(r0 + q) = __halves2half2(h00, h01);
            *(__half2*)(r1 + q) = __halves2half2(h10, h11);
            float v00 = __half2float(h00), v01 = __half2float(h01);
            float v10 = __half2float(h10), v11 = __half2float(h11);
            rs0[mi] += v00 + v01; rs1[mi] += v10 + v11;
            ccx[ni] += v00 + v10; ccy[ni] += v01 + v11;
        }
    }
#pragma unroll
    for (int mi = 0; mi < 4; ++mi) {
        float a = rs0[mi], c2 = rs1[mi];
        a  += __shfl_xor_sync(0xffffffffu, a, 1);  a  += __shfl_xor_sync(0xffffffffu, a, 2);
        c2 += __shfl_xor_sync(0xffffffffu, c2, 1); c2 += __shfl_xor_sync(0xffffffffu, c2, 2);
        if (t == 0) {
            int cA = c0 + mbase + mi * 16 + g;
            atomicAdd(&g_rsum[b * LCc + cA], a);
            atomicAdd(&g_rsum[b * LCc + cA + 8], c2);
        }
    }
#pragma unroll
    for (int ni = 0; ni < 4; ++ni) {
        float x = ccx[ni], y = ccy[ni];
        x += __shfl_xor_sync(0xffffffffu, x, 4);  y += __shfl_xor_sync(0xffffffffu, y, 4);
        x += __shfl_xor_sync(0xffffffffu, x, 8);  y += __shfl_xor_sync(0xffffffffu, y, 8);
        x += __shfl_xor_sync(0xffffffffu, x, 16); y += __shfl_xor_sync(0xffffffffu, y, 16);
        if (g == 0) {
            int q = q0 + nbase + ni * 8 + 2 * t;
            atomicAdd(&g_csum2[b * LQq + q], x);
            atomicAdd(&g_csum2[b * LQq + q + 1], y);
        }
    }
}

// ---- k4: M2 = (E^T @ C / colsum); plain [k][m]/[k][n] tiles + ldmatrix.trans ---
__global__ __launch_bounds__(256, 2) void k4_M() {
    __shared__ __half As[2][32][136];   // [k=c rows][m=q cols], stride 272 B
    __shared__ __half Bs[2][32][136];   // [k=c rows][n=d cols]
    const int b = blockIdx.z, q0 = blockIdx.y * 128, d0 = blockIdx.x * 128;
    const int tid = threadIdx.x, lane = tid & 31, w = tid >> 5;
    const int g = lane >> 2, t = lane & 3;
    const int mbase = (w >> 2) * 64, nbase = (w & 3) * 32;
    const int row = tid >> 3, seg = (tid & 7) * 16;
    const __half* Ag = g_Eh + (size_t)(b * LCc + row) * LQq + q0 + seg;
    const __half* Bg = g_Ch + ((size_t)row * NB + b) * ND + d0 + seg;
    const u32 Ad = smem_u32(&As[0][row][seg]);
    const u32 Bd = smem_u32(&Bs[0][row][seg]);
    const int lj = lane >> 3, li = lane & 7;
    const u32 A0 = smem_u32(&As[0][0][0]);
    const u32 B0 = smem_u32(&Bs[0][0][0]);
    const size_t Astep = (size_t)32 * LQq;
    const size_t Bstep = (size_t)32 * NB * ND;
    // full staging: 16 halves (32 B) per thread per tile = 2 x cpa16 each
    cpa16(Ad, Ag); cpa16(Ad + 16, Ag + 8);
    cpa16(Bd, Bg); cpa16(Bd + 16, Bg + 8);
    cpa_commit();
    float4 acc[4][4] = {};
    for (int ch = 0; ch < 32; ++ch) {
        const int p = ch & 1;
        if (ch < 31) {
            const u32 off = (u32)((p ^ 1) * 8704);
            cpa16(Ad + off, Ag + (size_t)(ch + 1) * Astep);
            cpa16(Ad + off + 16, Ag + (size_t)(ch + 1) * Astep + 8);
            cpa16(Bd + off, Bg + (size_t)(ch + 1) * Bstep);
            cpa16(Bd + off + 16, Bg + (size_t)(ch + 1) * Bstep + 8);
            cpa_commit();
            cpa_wait<1>();
        } else cpa_wait<0>();
        __syncthreads();
#pragma unroll
        for (int s = 0; s < 2; ++s) {
            u32 af[4][4], bf[4][2];
            // A matrices: j0=(k-lo,m-lo) j1=(k-lo,m+8) j2=(k-hi,m-lo) j3=(k-hi,m+8)
            u32 abase = A0 + (u32)p * 8704
                + (u32)((16 * s + ((lj >> 1) << 3) + li) * 272 + (mbase + ((lj & 1) << 3)) * 2);
#pragma unroll
            for (int mi = 0; mi < 4; ++mi)
                ldsm_x4t(af[mi][0], af[mi][1], af[mi][2], af[mi][3], abase + mi * 32);
            // B matrices: j0=(k-lo,n) j1=(k-hi,n) j2=(k-lo,n+8) j3=(k-hi,n+8)
            u32 bbase = B0 + (u32)p * 8704
                + (u32)((16 * s + ((lj & 1) << 3) + li) * 272 + (nbase + ((lj >> 1) << 3)) * 2);
#pragma unroll
            for (int nj = 0; nj < 2; ++nj)
                ldsm_x4t(bf[2 * nj][0], bf[2 * nj][1], bf[2 * nj + 1][0], bf[2 * nj + 1][1],
                         bbase + nj * 32);
#pragma unroll
            for (int mi = 0; mi < 4; ++mi)
#pragma unroll
                for (int ni = 0; ni < 4; ++ni)
                    mma16(acc[mi][ni], af[mi][0], af[mi][1], af[mi][2], af[mi][3],
                          bf[ni][0], bf[ni][1]);
        }
        __syncthreads();
    }
#pragma unroll
    for (int mi = 0; mi < 4; ++mi) {
        int qA = q0 + mbase + mi * 16 + g;
        float i0 = 1.0f / g_csum2[b * LQq + qA];
        float i1 = 1.0f / g_csum2[b * LQq + qA + 8];
        size_t m0b = ((size_t)(b * (LQq / 2) + (qA >> 1)) * ND + d0) * 2 + (qA & 1);
        size_t m1b = m0b + (size_t)8 * ND;
#pragma unroll
        for (int ni = 0; ni < 4; ++ni) {
            int d = nbase + ni * 8 + 2 * t;
            g_M2[m0b + 2 * d]     = h_rn(acc[mi][ni].x * i0);
            g_M2[m0b + 2 * d + 2] = h_rn(acc[mi][ni].y * i0);
            g_M2[m1b + 2 * d]     = h_rn(acc[mi][ni].z * i1);
            g_M2[m1b + 2 * d + 2] = h_rn(acc[mi][ni].w * i1);
        }
    }
}

// ---- k5: A = S1@Q, B_ = S1@M (unchanged, proven); transposed concat ------------
__global__ __launch_bounds__(256, 2) void k5_out(const float* __restrict__ C,
                                                 float* __restrict__ out) {
    __shared__ __align__(16) char sm5[38912];
    __half (*As)[128][40] = (__half(*)[128][40])sm5;
    __half (*Bq)[16][144] = (__half(*)[16][144])(sm5 + 20480);
    __half (*Bm)[16][144] = (__half(*)[16][144])(sm5 + 29696);
    float (*Cs)[65]       = (float(*)[65])sm5;
    float (*Tr)[69]       = (float(*)[69])(sm5 + 16640);
    const int b = blockIdx.z, c0 = blockIdx.y * 128, d0 = blockIdx.x * 64;
    const int tid = threadIdx.x, lane = tid & 31, w = tid >> 5;
    const int g = lane >> 2, t = lane & 3;
    const int wr = w >> 1, wc = w & 1;
    const int mbase = wr * 32, nbase = wc * 32;
    const int rowc = tid >> 1, sgA = (tid & 1) * 16;
    const int k2r = tid >> 4, sgB = (tid & 15) * 8;
    const __half* Ag = g_Eh + (size_t)(b * LCc + c0 + rowc) * LQq + sgA;
    const __half* Qg = g_Q2 + ((size_t)(k2r * NB + b) * ND + d0) * 2 + sgB;
    const __half* Mg = g_M2 + ((size_t)(b * (LQq / 2) + k2r) * ND + d0) * 2 + sgB;
    const u32 Ad  = smem_u32(&As[0][rowc][sgA]);
    const u32 Bqd = smem_u32(&Bq[0][k2r][sgB]);
    const u32 Bmd = smem_u32(&Bm[0][k2r][sgB]);
    cpa16(Ad, Ag); cpa16(Ad + 16, Ag + 8);
    cpa16(Bqd, Qg); cpa16(Bmd, Mg);
    cpa_commit();
    float4 accA[2][4] = {}, accB[2][4] = {};
    for (int ch = 0; ch < 16; ++ch) {
        const int p = ch & 1;
        if (ch < 15) {
            const int ko = (ch + 1) * 32;
            const u32 offA = (u32)((p ^ 1) * 10240);
            const u32 offB = (u32)((p ^ 1) * 4608);
            cpa16(Ad + offA, Ag + ko); cpa16(Ad + offA + 16, Ag + ko + 8);
            cpa16(Bqd + offB, Qg + (size_t)(ch + 1) * 16 * ((size_t)NB * ND * 2));
            cpa16(Bmd + offB, Mg + (size_t)(ch + 1) * 16 * (ND * 2));
            cpa_commit();
            cpa_wait<1>();
        } else cpa_wait<0>();
        __syncthreads();
#pragma unroll
        for (int s = 0; s < 2; ++s) {
            u32 af[2][4], qf[4][2], mf[4][2];
#pragma unroll
            for (int mi = 0; mi < 2; ++mi) {
                int m = mbase + mi * 16 + g;
                af[mi][0] = *(const u32*)&As[p][m][16 * s + 2 * t];
                af[mi][1] = *(const u32*)&As[p][m + 8][16 * s + 2 * t];
                af[mi][2] = *(const u32*)&As[p][m][16 * s + 2 * t + 8];
                af[mi][3] = *(const u32*)&As[p][m + 8][16 * s + 2 * t + 8];
            }
#pragma unroll
            for (int ni = 0; ni < 4; ++ni) {
                int n = nbase + ni * 8 + g;
                qf[ni][0] = *(const u32*)&Bq[p][8 * s + t][2 * n];
                qf[ni][1] = *(const u32*)&Bq[p][8 * s + t + 4][2 * n];
                mf[ni][0] = *(const u32*)&Bm[p][8 * s + t][2 * n];
                mf[ni][1] = *(const u32*)&Bm[p][8 * s + t + 4][2 * n];
            }
#pragma unroll
            for (int mi = 0; mi < 2; ++mi)
#pragma unroll
                for (int ni = 0; ni < 4; ++ni) {
                    mma16(accA[mi][ni], af[mi][0], af[mi][1], af[mi][2], af[mi][3],
                          qf[ni][0], qf[ni][1]);
                    mma16(accB[mi][ni], af[mi][0], af[mi][1], af[mi][2], af[mi][3],
                          mf[ni][0], mf[ni][1]);
                }
        }
        __syncthreads();
    }
#pragma unroll
    for (int mi = 0; mi < 2; ++mi) {
        int cA = c0 + mbase + mi * 16 + g;
        float i0 = 1.0f / g_rsum[b * LCc + cA];
        float i1 = 1.0f / g_rsum[b * LCc + cA + 8];
#pragma unroll
        for (int ni = 0; ni < 4; ++ni) {
            accA[mi][ni].x *= i0; accA[mi][ni].y *= i0;
            accA[mi][ni].z *= i1; accA[mi][ni].w *= i1;
            accB[mi][ni].x *= i0; accB[mi][ni].y *= i0;
            accB[mi][ni].z *= i1; accB[mi][ni].w *= i1;
        }
    }
    const int cl = tid & 63, dseg = (tid >> 6) * 16;
    const int cr = tid & 63, db = tid >> 6;
    const size_t ob = (size_t)b * (4 * ND) * LCc;
    for (int h = 0; h < 2; ++h) {
        __syncthreads();
        {
            const float* Cg = C + (size_t)(c0 + h * 64 + cl) * (NB * ND) + (size_t)b * ND + d0 + dseg;
#pragma unroll
            for (int dd = 0; dd < 16; dd += 4) {
                float4 cv = *(const float4*)(Cg + dd);
                Cs[dseg + dd + 0][cl] = cv.x; Cs[dseg + dd + 1][cl] = cv.y;
                Cs[dseg + dd + 2][cl] = cv.z; Cs[dseg + dd + 3][cl] = cv.w;
            }
        }
        if ((w >> 2) == h) {
#pragma unroll
            for (int mi = 0; mi < 2; ++mi) {
                int clh = (wr & 1) * 32 + mi * 16 + g;
#pragma unroll
                for (int ni = 0; ni < 4; ++ni) {
                    int d = nbase + ni * 8 + 2 * t;
                    Tr[clh][d] = accA[mi][ni].x;     Tr[clh][d + 1] = accA[mi][ni].y;
                    Tr[clh + 8][d] = accA[mi][ni].z; Tr[clh + 8][d + 1] = accA[mi][ni].w;
                }
            }
        }
        __syncthreads();
#pragma unroll
        for (int rr = 0; rr < 16; ++rr) {
            int dr = db + rr * 4;
            float cval = Cs[dr][cr];
            float aval = Tr[cr][dr];
            size_t col = (size_t)(c0 + h * 64 + cr);
            out[ob + (size_t)(d0 + dr) * LCc + col]          = cval;
            out[ob + (size_t)(ND + d0 + dr) * LCc + col]     = aval;
            out[ob + (size_t)(2 * ND + d0 + dr) * LCc + col] = cval * aval;
        }
        __syncthreads();
        if ((w >> 2) == h) {
#pragma unroll
            for (int mi = 0; mi < 2; ++mi) {
                int clh = (wr & 1) * 32 + mi * 16 + g;
#pragma unroll
                for (int ni = 0; ni < 4; ++ni) {
                    int d = nbase + ni * 8 + 2 * t;
                    Tr[clh][d] = accB[mi][ni].x;     Tr[clh][d + 1] = accB[mi][ni].y;
                    Tr[clh + 8][d] = accB[mi][ni].z; Tr[clh + 8][d + 1] = accB[mi][ni].w;
                }
            }
        }
        __syncthreads();
#pragma unroll
        for (int rr = 0; rr < 16; ++rr) {
            int dr = db + rr * 4;
            out[ob + (size_t)(3 * ND + d0 + dr) * LCc + (size_t)(c0 + h * 64 + cr)] =
                Cs[dr][cr] * Tr[cr][dr];
        }
    }
}

extern "C" void kernel_launch(void* const* d_in, const int* in_sizes, int n_in,
                              void* d_out, int out_size) {
    const float* C     = (const float*)d_in[0];
    const float* Q     = (const float*)d_in[1];
    const float* w4C   = (const float*)d_in[2];
    const float* w4Q   = (const float*)d_in[3];
    const float* w4mlu = (const float*)d_in[4];
    const float* bias  = (const float*)d_in[5];
    float* out = (float*)d_out;

    k_init<<<(NB * LCc + 255) / 256, 256>>>();
    k0_all<<<12288, 256>>>(C, Q, w4C, w4Q, w4mlu);
    k1_scores<<<dim3(LQq / 128, LCc / 128, NB), 256>>>(bias);
    k4_M<<<dim3(ND / 128, LQq / 128, NB), 256>>>();
    k5_out<<<dim3(ND / 64, LCc / 128, NB), 256>>>(C, out);
}